// round 7
// baseline (speedup 1.0000x reference)
#include <cuda_runtime.h>
#include <cuda_bf16.h>
#include <math.h>

// ---------------------------------------------------------------------------
// Struct2SeqGCN: CGConv x4 + BN + LN blocks + final LN + FC
// N=20000 nodes, E=320000 edges, H=128, 4 layers, 16 RBF gaussians
// ---------------------------------------------------------------------------

#define NMAX   20000
#define EMAX   320000
#define HID    128
#define NBINS  2048            // lerp table bins (rows = NBINS+1)
#define NPART  157             // ceil(20000/128)

// ------------------------- static scratch (no allocs) ----------------------
__device__ __align__(16) float g_h   [NMAX * HID];        // node features
__device__ __align__(16) float g_AB  [NMAX * 4 * HID];    // [Af | Bf | As | Bs]
__device__ __align__(16) float g_agg [NMAX * HID];        // aggregated messages
__device__ __align__(16) float g_Tf  [(NBINS + 1) * HID]; // lerp table (f gate)
__device__ __align__(16) float g_Ts  [(NBINS + 1) * HID]; // lerp table (s gate)
__device__ int   g_degcur[2 * NMAX];                      // [deg | cur], one zeroing
__device__ int   g_rowptr[NMAX + 1];
__device__ int   g_csrc[EMAX];
__device__ float g_cpos[EMAX];
__device__ __align__(16) float g_part[NPART * 2 * HID];   // BN partials
__device__ __align__(16) float g_bns [2 * HID];           // BN fused scale/shift

// ------------------------------ helpers ------------------------------------
__device__ __forceinline__ float fsigmoid(float x) {
    return __fdividef(1.0f, 1.0f + __expf(-x));
}
__device__ __forceinline__ float fsoftplus(float x) {
    return fmaxf(x, 0.0f) + __logf(1.0f + __expf(-fabsf(x)));
}

// ------------------------------ CSR build ----------------------------------
__global__ void zero_kernel(int* a, int n) {
    int i = blockIdx.x * blockDim.x + threadIdx.x;
    if (i < n) a[i] = 0;
}

__global__ void hist_kernel(const int* __restrict__ ei, int* __restrict__ deg, int E) {
    int e = blockIdx.x * blockDim.x + threadIdx.x;
    if (e < E) atomicAdd(&deg[ei[E + e]], 1);   // row 1 = dst
}

__global__ void scan_kernel(const int* __restrict__ deg, int* __restrict__ rowptr, int n) {
    __shared__ int wsum[32];
    __shared__ int carry;
    if (threadIdx.x == 0) carry = 0;
    __syncthreads();
    int lane = threadIdx.x & 31, wid = threadIdx.x >> 5;
    for (int base = 0; base < n; base += 1024) {
        int i = base + (int)threadIdx.x;
        int v = (i < n) ? deg[i] : 0;
        int x = v;
        #pragma unroll
        for (int d = 1; d < 32; d <<= 1) {
            int y = __shfl_up_sync(0xffffffffu, x, d);
            if (lane >= d) x += y;
        }
        if (lane == 31) wsum[wid] = x;
        __syncthreads();
        if (wid == 0) {
            int s = wsum[lane];
            #pragma unroll
            for (int d = 1; d < 32; d <<= 1) {
                int y = __shfl_up_sync(0xffffffffu, s, d);
                if (lane >= d) s += y;
            }
            wsum[lane] = s;
        }
        __syncthreads();
        int pre  = (wid > 0) ? wsum[wid - 1] : 0;
        int incl = x + pre;
        int c0   = carry;
        if (i < n) rowptr[i] = c0 + incl - v;   // exclusive
        __syncthreads();
        if (threadIdx.x == 1023) carry = c0 + incl;
        __syncthreads();
    }
    if (threadIdx.x == 0) rowptr[n] = carry;
}

__global__ void scatter_kernel(const int* __restrict__ ei, const float* __restrict__ dist,
                               const int* __restrict__ rowptr, int* __restrict__ cur,
                               int* __restrict__ csrc, float* __restrict__ cpos, int E) {
    int e = blockIdx.x * blockDim.x + threadIdx.x;
    if (e >= E) return;
    int s = ei[e];
    int d = ei[E + e];
    int pos = rowptr[d] + atomicAdd(&cur[d], 1);
    csrc[pos] = s;
    float p = dist[e] * ((float)NBINS / 8.0f);
    cpos[pos] = fminf(fmaxf(p, 0.0f), (float)NBINS - 0.001f);
}

// --------------------------- node embedding --------------------------------
__global__ void embed_kernel(const float* __restrict__ x, const float* __restrict__ W,
                             const float* __restrict__ b, float* __restrict__ h, int N) {
    int i = blockIdx.x * blockDim.x + threadIdx.x;
    if (i >= N * HID) return;
    int n = i >> 7, c = i & 127;
    float acc = b[c];
    #pragma unroll
    for (int k = 0; k < 6; k++) acc += x[n * 6 + k] * W[k * HID + c];
    h[i] = acc;
}

// ----------------------- edge RBF lerp table build -------------------------
// Tf[b][c] = bf[c] + sum_g exp(COEFF*(d_b-off_g)^2) * Wf_edge[g][c]
__global__ void table_kernel(const float* __restrict__ Wfe, const float* __restrict__ bf,
                             const float* __restrict__ Wse, const float* __restrict__ bs,
                             float* __restrict__ Tf, float* __restrict__ Ts) {
    int b = blockIdx.x;          // 0..NBINS
    int c = threadIdx.x;         // 0..127
    float d = (float)b * (8.0f / (float)NBINS);
    float af = bf[c], as = bs[c];
    #pragma unroll
    for (int g = 0; g < 16; g++) {
        float off = (float)g * (8.0f / 15.0f);
        float t = d - off;
        float e = expf(-1.7578125f * t * t);   // COEFF = -0.5/(8/15)^2
        af += e * Wfe[g * HID + c];
        as += e * Wse[g * HID + c];
    }
    Tf[b * HID + c] = af;
    Ts[b * HID + c] = as;
}

// ------------------ node precompute GEMM: h[Nx128] @ W[128x512] ------------
// part 0: Wf dst-part -> Af   part 1: Wf src-part -> Bf
// part 2: Ws dst-part -> As   part 3: Ws src-part -> Bs
// C layout per node row: [Af | Bf | As | Bs] (512 floats)
__global__ __launch_bounds__(256)
void sgemm_kernel(const float* __restrict__ A, const float* __restrict__ Wfl,
                  const float* __restrict__ Wsl, float* __restrict__ C, int M) {
    __shared__ float As_[16][132];
    __shared__ float Bs_[16][128];
    int part = blockIdx.y;
    const float* Bpart = ((part < 2) ? Wfl : Wsl) + (part & 1) * (HID * HID);
    int m0  = blockIdx.x * 128;
    int tid = threadIdx.x;
    int tm = tid >> 4, tn = tid & 15;
    float acc[8][8] = {};

    for (int k0 = 0; k0 < 128; k0 += 16) {
        // load A tile 128x16 (float4 along k), store transposed
        int r  = tid >> 2;
        int kq = (tid & 3) * 4;
        #pragma unroll
        for (int rr = 0; rr < 2; rr++) {
            int row = r + rr * 64;
            int gm  = m0 + row;
            float4 v = (gm < M) ? *(const float4*)(A + (size_t)gm * HID + k0 + kq)
                                : make_float4(0.f, 0.f, 0.f, 0.f);
            As_[kq + 0][row] = v.x; As_[kq + 1][row] = v.y;
            As_[kq + 2][row] = v.z; As_[kq + 3][row] = v.w;
        }
        // load B tile 16x128 (float4 along n)
        int kk = tid >> 5;
        int j  = (tid & 31) * 4;
        #pragma unroll
        for (int rr = 0; rr < 2; rr++) {
            float4 v = *(const float4*)(Bpart + (size_t)(k0 + kk + rr * 8) * HID + j);
            *(float4*)&Bs_[kk + rr * 8][j] = v;
        }
        __syncthreads();
        #pragma unroll
        for (int kki = 0; kki < 16; kki++) {
            float a[8], bb[8];
            *(float4*)&a[0]  = *(float4*)&As_[kki][tm * 8];
            *(float4*)&a[4]  = *(float4*)&As_[kki][tm * 8 + 4];
            *(float4*)&bb[0] = *(float4*)&Bs_[kki][tn * 8];
            *(float4*)&bb[4] = *(float4*)&Bs_[kki][tn * 8 + 4];
            #pragma unroll
            for (int i = 0; i < 8; i++)
                #pragma unroll
                for (int jj = 0; jj < 8; jj++)
                    acc[i][jj] += a[i] * bb[jj];
        }
        __syncthreads();
    }
    #pragma unroll
    for (int i = 0; i < 8; i++) {
        int gm = m0 + tm * 8 + i;
        if (gm < M) {
            float* cp = C + (size_t)gm * 512 + part * 128 + tn * 8;
            *(float4*)cp       = make_float4(acc[i][0], acc[i][1], acc[i][2], acc[i][3]);
            *(float4*)(cp + 4) = make_float4(acc[i][4], acc[i][5], acc[i][6], acc[i][7]);
        }
    }
}

// --------------------- edge message + aggregation (CSR) --------------------
__global__ __launch_bounds__(256)
void agg_kernel(const float* __restrict__ AB, const int* __restrict__ rowptr,
                const int* __restrict__ csrc, const float* __restrict__ cpos,
                const float* __restrict__ Tf, const float* __restrict__ Ts,
                float* __restrict__ agg, int N) {
    int warp = (blockIdx.x * blockDim.x + threadIdx.x) >> 5;
    if (warp >= N) return;
    int lane = threadIdx.x & 31;
    const float4* ABv = (const float4*)AB;  // 128 float4 per node row

    float4 af  = ABv[(size_t)warp * 128 + lane];        // Af: floats [0,128)
    float4 as_ = ABv[(size_t)warp * 128 + 64 + lane];   // As: floats [256,384)
    float4 acc = make_float4(0.f, 0.f, 0.f, 0.f);

    int beg = rowptr[warp], end = rowptr[warp + 1];
    #pragma unroll 2
    for (int i = beg; i < end; i++) {
        int   s = csrc[i];
        float p = cpos[i];
        int   k = (int)p;
        float t = p - (float)k;
        float4 bf = ABv[(size_t)s * 128 + 32 + lane];   // Bf: floats [128,256)
        float4 bs = ABv[(size_t)s * 128 + 96 + lane];   // Bs: floats [384,512)
        const float4* tf = (const float4*)(Tf + (size_t)k * HID) + lane;
        const float4* ts = (const float4*)(Ts + (size_t)k * HID) + lane;
        float4 f0 = tf[0],  f1 = tf[32];
        float4 s0 = ts[0],  s1 = ts[32];

        float fx = af.x + bf.x + f0.x + t * (f1.x - f0.x);
        float fy = af.y + bf.y + f0.y + t * (f1.y - f0.y);
        float fz = af.z + bf.z + f0.z + t * (f1.z - f0.z);
        float fw = af.w + bf.w + f0.w + t * (f1.w - f0.w);
        float sx = as_.x + bs.x + s0.x + t * (s1.x - s0.x);
        float sy = as_.y + bs.y + s0.y + t * (s1.y - s0.y);
        float sz = as_.z + bs.z + s0.z + t * (s1.z - s0.z);
        float sw = as_.w + bs.w + s0.w + t * (s1.w - s0.w);

        acc.x += fsigmoid(fx) * fsoftplus(sx);
        acc.y += fsigmoid(fy) * fsoftplus(sy);
        acc.z += fsigmoid(fz) * fsoftplus(sz);
        acc.w += fsigmoid(fw) * fsoftplus(sw);
    }
    ((float4*)agg)[(size_t)warp * 32 + lane] = acc;
}

// --------------------------- BatchNorm stats -------------------------------
__global__ void bn_part_kernel(const float* __restrict__ agg, float* __restrict__ part, int N) {
    int c = threadIdx.x;            // 128
    int b = blockIdx.x;             // NPART
    int r0 = b * 128, r1 = min(r0 + 128, N);
    float s = 0.f, q = 0.f;
    for (int r = r0; r < r1; r++) {
        float v = agg[(size_t)r * HID + c];
        s += v; q += v * v;
    }
    part[b * 256 + c]       = s;
    part[b * 256 + 128 + c] = q;
}

__global__ void bn_fin_kernel(const float* __restrict__ part, const float* __restrict__ g,
                              const float* __restrict__ b, float* __restrict__ sb,
                              int nb, int N) {
    int c = threadIdx.x;
    float s = 0.f, q = 0.f;
    for (int i = 0; i < nb; i++) {
        s += part[i * 256 + c];
        q += part[i * 256 + 128 + c];
    }
    float invN = 1.0f / (float)N;
    float mu  = s * invN;
    float var = fmaxf(q * invN - mu * mu, 0.0f);
    float sc  = g[c] * rsqrtf(var + 1e-5f);
    sb[c]       = sc;
    sb[128 + c] = b[c] - mu * sc;
}

// ---------------- BN-apply + residual + LayerNorm + ReLU + residual --------
__global__ __launch_bounds__(256)
void update_kernel(float* __restrict__ h, const float* __restrict__ agg,
                   const float* __restrict__ sb, const float* __restrict__ lng,
                   const float* __restrict__ lnb, int N) {
    int warp = (blockIdx.x * blockDim.x + threadIdx.x) >> 5;
    if (warp >= N) return;
    int lane = threadIdx.x & 31;
    float4 a  = ((const float4*)agg)[(size_t)warp * 32 + lane];
    float4 hv = ((const float4*)h)  [(size_t)warp * 32 + lane];
    float4 sc = ((const float4*)sb)[lane];
    float4 sh = ((const float4*)sb)[32 + lane];

    float cx = a.x * sc.x + sh.x + hv.x;
    float cy = a.y * sc.y + sh.y + hv.y;
    float cz = a.z * sc.z + sh.z + hv.z;
    float cw = a.w * sc.w + sh.w + hv.w;

    float sum = cx + cy + cz + cw;
    #pragma unroll
    for (int d = 16; d; d >>= 1) sum += __shfl_xor_sync(0xffffffffu, sum, d);
    float m = sum * (1.0f / 128.0f);

    float dx = cx - m, dy = cy - m, dz = cz - m, dw = cw - m;
    float q = dx * dx + dy * dy + dz * dz + dw * dw;
    #pragma unroll
    for (int d = 16; d; d >>= 1) q += __shfl_xor_sync(0xffffffffu, q, d);
    float r = rsqrtf(q * (1.0f / 128.0f) + 1e-5f);

    float4 g4 = ((const float4*)lng)[lane];
    float4 b4 = ((const float4*)lnb)[lane];
    float4 o;
    o.x = fmaxf(dx * r * g4.x + b4.x, 0.f) + hv.x;
    o.y = fmaxf(dy * r * g4.y + b4.y, 0.f) + hv.y;
    o.z = fmaxf(dz * r * g4.z + b4.z, 0.f) + hv.z;
    o.w = fmaxf(dw * r * g4.w + b4.w, 0.f) + hv.w;
    ((float4*)h)[(size_t)warp * 32 + lane] = o;
}

// ----------------------- final LayerNorm + FC ------------------------------
__global__ __launch_bounds__(128)
void out_kernel(const float* __restrict__ h, const float* __restrict__ g,
                const float* __restrict__ b, const float* __restrict__ Wfc,
                const float* __restrict__ bfc, float* __restrict__ out, int N) {
    __shared__ float sh[128];
    __shared__ float red[4];
    int n = blockIdx.x, c = threadIdx.x;
    int wid = c >> 5, lane = c & 31;
    float v = h[(size_t)n * HID + c];

    float s = v;
    #pragma unroll
    for (int d = 16; d; d >>= 1) s += __shfl_xor_sync(0xffffffffu, s, d);
    if (lane == 0) red[wid] = s;
    __syncthreads();
    float m = (red[0] + red[1] + red[2] + red[3]) * (1.0f / 128.0f);
    __syncthreads();

    float dv = v - m;
    float q = dv * dv;
    #pragma unroll
    for (int d = 16; d; d >>= 1) q += __shfl_xor_sync(0xffffffffu, q, d);
    if (lane == 0) red[wid] = q;
    __syncthreads();
    float var = (red[0] + red[1] + red[2] + red[3]) * (1.0f / 128.0f);

    float hn = dv * rsqrtf(var + 1e-5f) * g[c] + b[c];
    sh[c] = hn;
    __syncthreads();

    if (c < 21) {
        float acc = bfc[c];
        #pragma unroll 4
        for (int k = 0; k < 128; k++) acc += sh[k] * Wfc[k * 21 + c];
        out[(size_t)n * 21 + c] = acc;
    }
}

// ------------------------------- launch ------------------------------------
extern "C" void kernel_launch(void* const* d_in, const int* in_sizes, int n_in,
                              void* d_out, int out_size) {
    const float* x     = (const float*)d_in[0];
    const int*   ei    = (const int*)  d_in[1];
    const float* dist  = (const float*)d_in[2];
    const float* Wn    = (const float*)d_in[3];
    const float* bn    = (const float*)d_in[4];
    const float* Wf    = (const float*)d_in[5];
    const float* bf    = (const float*)d_in[6];
    const float* Ws    = (const float*)d_in[7];
    const float* bs    = (const float*)d_in[8];
    const float* bng   = (const float*)d_in[9];
    const float* bnb   = (const float*)d_in[10];
    const float* lng   = (const float*)d_in[11];
    const float* lnb   = (const float*)d_in[12];
    const float* lnog  = (const float*)d_in[13];
    const float* lnob  = (const float*)d_in[14];
    const float* Wfc   = (const float*)d_in[15];
    const float* bfc   = (const float*)d_in[16];

    const int N = in_sizes[0] / 6;        // 20000
    const int E = in_sizes[2];            // 320000
    const int L = in_sizes[6] / HID;      // 4
    const int Z = 2 * HID + 16;           // 272

    float* h      = g_h;
    float* AB     = g_AB;
    float* agg    = g_agg;
    int*   deg    = g_degcur;             // [0, N)
    int*   cur    = g_degcur + NMAX;      // [NMAX, NMAX+N) — one array, one zeroing
    int*   rowptr = g_rowptr;

    // --- CSR build (once; edge_index is layer-invariant) ---
    zero_kernel<<<(2 * NMAX + 255) / 256, 256>>>(g_degcur, 2 * NMAX);
    hist_kernel<<<(E + 255) / 256, 256>>>(ei, deg, E);
    scan_kernel<<<1, 1024>>>(deg, rowptr, N);
    scatter_kernel<<<(E + 255) / 256, 256>>>(ei, dist, rowptr, cur, g_csrc, g_cpos, E);

    // --- initial node embedding ---
    embed_kernel<<<(N * HID + 255) / 256, 256>>>(x, Wn, bn, h, N);

    const int mtiles = (N + 127) / 128;
    const int wblocks = (N * 32 + 255) / 256;

    for (int l = 0; l < L; l++) {
        const float* Wfl = Wf + (size_t)l * Z * HID;
        const float* Wsl = Ws + (size_t)l * Z * HID;
        // node precompute [Af|Bf|As|Bs]
        sgemm_kernel<<<dim3(mtiles, 4), 256>>>(h, Wfl, Wsl, AB, N);
        // edge-term lerp tables (bias folded in)
        table_kernel<<<NBINS + 1, HID>>>(Wfl + 256 * HID, bf + l * HID,
                                         Wsl + 256 * HID, bs + l * HID, g_Tf, g_Ts);
        // gated message + segment-sum
        agg_kernel<<<wblocks, 256>>>(AB, rowptr, g_csrc, g_cpos, g_Tf, g_Ts, agg, N);
        // BatchNorm over nodes
        bn_part_kernel<<<(N + 127) / 128, HID>>>(agg, g_part, N);
        bn_fin_kernel<<<1, HID>>>(g_part, bng + l * HID, bnb + l * HID,
                                  g_bns, (N + 127) / 128, N);
        // residual + LN + ReLU + residual
        update_kernel<<<wblocks, 256>>>(h, agg, g_bns, lng + l * HID, lnb + l * HID, N);
    }

    // final LN + FC
    out_kernel<<<N, HID>>>(h, lnog, lnob, Wfc, bfc, (float*)d_out, N);
}